// round 9
// baseline (speedup 1.0000x reference)
#include <cuda_runtime.h>
#include <math.h>

#define DCH   128
#define BE    1024
#define NF    128
#define NS    32768
#define NT    256      // threads per CTA

// Dynamic smem (floats). xp layout per layer-input: float2 entries
//   xp[k] = (x[k-1], x[k]),  k = 0..L  (x[-1]=x[L]=0), row stride in floats:
//   up-proj out: 20 (S2=10), L1 out: 36 (S2=18), L2 out: 68 (S2=34),
//   L3 out: natural floats, stride 68.
#define A_OFF    0
#define A_SIZE   (128*68)     // up-proj xp (20/row) then L2-out xp (68/row)
#define B_OFF    (A_OFF + A_SIZE)
#define B_SIZE   (128*68)     // L1-out xp (36/row) then L3-out natural (68/row)
#define XF_OFF   (B_OFF + B_SIZE)
#define XFP_OFF  (XF_OFF + 128)
#define VS_OFF   (XFP_OFF + 256)
#define VD_OFF   (VS_OFF + 128)
#define PART_OFF (VD_OFF + 256)
#define SMEM_FLOATS (PART_OFF + 256)
#define SMEM_BYTES  (SMEM_FLOATS * 4)

typedef unsigned long long u64;

__device__ __forceinline__ float leaky(float v) { return v > 0.f ? v : 0.2f * v; }

__device__ __forceinline__ void upk(u64 v, float& a, float& b) {
    asm("mov.b64 {%0,%1}, %2;" : "=f"(a), "=f"(b) : "l"(v));
}
__device__ __forceinline__ u64 pk(float a, float b) {
    u64 r; asm("mov.b64 %0, {%1,%2};" : "=l"(r) : "f"(a), "f"(b)); return r;
}
__device__ __forceinline__ void f2fma(u64& d, u64 a, u64 b) {
    asm("fma.rn.f32x2 %0, %1, %2, %0;" : "+l"(d) : "l"(a), "l"(b));
}

// Transposed conv (k=4, s=2, p=1), JAX conv_transpose (no flip):
//   y[2j]   = sum_ci x[j-1]*w0 + x[j]*w2
//   y[2j+1] = sum_ci x[j]  *w1 + x[j+1]*w3
// With xp[k]=(x[k-1],x[k]):  acc2[j] += xp[j]*(w0,w1) + xp[j+1]*(w2,w3).
// Thread (co, h in {0,1}) computes output pairs j in [h*NJ, (h+1)*NJ).
// SIN2  = input row stride in float2 entries.
// SOUTF = output row stride in floats.
// XPOUT: true -> write xp-pair layout (scalar stores); false -> natural float4.
template <int LIN, int SIN2, int SOUTF, bool XPOUT>
__device__ __forceinline__ void tconv2(
    const float* __restrict__ W, const float* __restrict__ bias,
    const float* __restrict__ xin, float* __restrict__ yout,
    int co, int h)
{
    constexpr int NJ = LIN / 2;      // output pairs per thread
    constexpr int NH = NJ / 2;       // ulonglong2 loads per ci
    const float bv = bias[co];
    u64 acc[NJ];
    {
        u64 bp = pk(bv, bv);
#pragma unroll
        for (int j = 0; j < NJ; ++j) acc[j] = bp;
    }
    const int j0 = h * NJ;           // first entry index (even)

    for (int ci = 0; ci < DCH; ++ci) {
        ulonglong2 wq = *(const ulonglong2*)(W + ((ci * DCH + co) << 2));
        const float* xrow = xin + ci * (2 * SIN2);
        const ulonglong2* xr2 = (const ulonglong2*)xrow + (j0 >> 1);
        const u64 elast = ((const u64*)xrow)[j0 + NJ];
        ulonglong2 q = xr2[0];
#pragma unroll
        for (int m = 0; m < NH; ++m) {
            ulonglong2 qn;
            if (m + 1 < NH) qn = xr2[m + 1];
            else { qn.x = elast; qn.y = 0ull; }
            f2fma(acc[2*m],   q.x,  wq.x);
            f2fma(acc[2*m],   q.y,  wq.y);
            f2fma(acc[2*m+1], q.y,  wq.x);
            f2fma(acc[2*m+1], qn.x, wq.y);
            q = qn;
        }
    }

    if (XPOUT) {
        // write pair layout: xp[k].y = y[k], xp[k+1].x = y[k]
        float* yf = yout + co * SOUTF;
#pragma unroll
        for (int j = 0; j < NJ; ++j) {
            float ya, yb;
            upk(acc[j], ya, yb);
            ya = leaky(ya); yb = leaky(yb);
            const int k0 = 2 * (j0 + j);
            yf[2*k0 + 1] = ya;
            yf[2*k0 + 2] = ya;
            yf[2*k0 + 3] = yb;
            yf[2*k0 + 4] = yb;
        }
        if (h == 0) yf[0] = 0.f;                       // xp[0].x = 0
        else        yf[4 * (j0 + NJ) + 1] = 0.f;       // xp[LOUT].y = 0
    } else {
        float* yr = yout + co * SOUTF + 2 * j0;
#pragma unroll
        for (int m = 0; m < NJ / 2; ++m) {
            float a0, a1, b0, b1;
            upk(acc[2*m],   a0, a1);
            upk(acc[2*m+1], b0, b1);
            float4 v;
            v.x = leaky(a0); v.y = leaky(a1);
            v.z = leaky(b0); v.w = leaky(b1);
            *(float4*)(yr + 4*m) = v;
        }
    }
}

__global__ void __launch_bounds__(NT, 3) npg_kernel(
    const float* __restrict__ x,    const float* __restrict__ noise,
    const float* __restrict__ Wup,  const float* __restrict__ bup,
    const float* __restrict__ Wd0,  const float* __restrict__ bd0,
    const float* __restrict__ Wd1,  const float* __restrict__ bd1,
    const float* __restrict__ Wd2,  const float* __restrict__ bd2,
    const float* __restrict__ Wdo,  const float* __restrict__ bdo,
    const float* __restrict__ Wc0,  const float* __restrict__ bc0,
    const float* __restrict__ Wc1,  const float* __restrict__ bc1,
    const float* __restrict__ Wc2,  const float* __restrict__ bc2,
    const float* __restrict__ Wc3,  const float* __restrict__ bc3,
    float* __restrict__ out)
{
    extern __shared__ float smem[];
    float*  A    = smem + A_OFF;
    float*  B    = smem + B_OFF;
    float*  xf   = smem + XF_OFF;
    float*  xfp  = smem + XFP_OFF;   // (x, x) duplicated pairs
    float*  vseq = smem + VS_OFF;
    float2* vd   = (float2*)(smem + VD_OFF);
    float*  part = smem + PART_OFF;
    __shared__ float s_decay;

    const int row  = blockIdx.x;
    const int t    = threadIdx.x;
    const int lane = t & 31;
    const int warp = t >> 5;
    const int co   = t & 127;
    const int h    = t >> 7;

    if (t < DCH) {
        float xv = x[row * DCH + t];
        xf[t] = xv;
        ((float2*)xfp)[t] = make_float2(xv, xv);
    }
    __syncthreads();

    // ---------------- decay head: 3x (D->D leaky) -> D->1 sigmoid ----------------
    {
        float* h0 = A;
        float* h1 = A + DCH;
        if (t < DCH) h0[t] = xf[t];
        __syncthreads();
        const float* Ws[3] = {Wd0, Wd1, Wd2};
        const float* bs[3] = {bd0, bd1, bd2};
        float* cur = h0;
        float* nxt = h1;
        for (int L = 0; L < 3; ++L) {
            const float* W = Ws[L];
            const int d0 = h * 64;
            float s0 = 0.f, s1 = 0.f, s2 = 0.f, s3 = 0.f;
            for (int dd = d0; dd < d0 + 64; dd += 4) {
                s0 += cur[dd+0] * W[(dd+0) * DCH + co];
                s1 += cur[dd+1] * W[(dd+1) * DCH + co];
                s2 += cur[dd+2] * W[(dd+2) * DCH + co];
                s3 += cur[dd+3] * W[(dd+3) * DCH + co];
            }
            part[t] = (s0 + s1) + (s2 + s3);
            __syncthreads();
            if (t < DCH) nxt[t] = leaky(bs[L][t] + part[t] + part[t + 128]);
            __syncthreads();
            float* tmp = cur; cur = nxt; nxt = tmp;
        }
        float p = (t < DCH) ? cur[t] * Wdo[t] : 0.f;
#pragma unroll
        for (int off = 16; off > 0; off >>= 1) p += __shfl_xor_sync(0xffffffffu, p, off);
        if (lane == 0) part[warp] = p;
        __syncthreads();
        if (t == 0) {
            float s = bdo[0];
            for (int wgi = 0; wgi < NT / 32; ++wgi) s += part[wgi];
            s_decay = 0.8f + 0.2f / (1.f + expf(-s));
        }
        __syncthreads();
    }

    // ------------- up projection: xf @ Wup -> xp pairs in A (stride 20 fl) -------
    // thread (co, h) computes output columns [4h, 4h+4)
    {
        float4 bvv = *(const float4*)(bup + co * 8 + 4 * h);
        u64 a01 = pk(bvv.x, bvv.y);
        u64 a23 = pk(bvv.z, bvv.w);
        const float* wr  = Wup + co * 8 + 4 * h;
        const u64*   xfq = (const u64*)xfp;
        for (int dd = 0; dd < DCH; ++dd) {
            ulonglong2 wq = *(const ulonglong2*)(wr + dd * (DCH * 8));
            u64 xx = xfq[dd];
            f2fma(a01, xx, wq.x);
            f2fma(a23, xx, wq.y);
        }
        __syncthreads();   // decay phase fully done with A
        float av[4];
        upk(a01, av[0], av[1]);
        upk(a23, av[2], av[3]);
        float* yf = A + co * 20;
#pragma unroll
        for (int qi = 0; qi < 4; ++qi) {
            const int k = 4 * h + qi;       // no activation on up-proj output
            yf[2*k + 1] = av[qi];
            yf[2*k + 2] = av[qi];
        }
        if (h == 0) yf[0] = 0.f;            // xp[0].x
        else        yf[17] = 0.f;           // xp[8].y
        __syncthreads();
    }

    // ---------------- transposed conv stack: 8 -> 16 -> 32 -> 64 -----------------
    tconv2<8,  10, 36, true >(Wc0, bc0, A, B, co, h);   // A xp(10) -> B xp(18)
    __syncthreads();
    tconv2<16, 18, 68, true >(Wc1, bc1, B, A, co, h);   // B xp(18) -> A xp(34)
    __syncthreads();
    tconv2<32, 34, 68, false>(Wc2, bc2, A, B, co, h);   // A xp(34) -> B natural
    __syncthreads();

    // ---------------- final tconv to 1 channel (64 -> 128), square ---------------
    {
        const int  p  = co;
        const int  j  = p >> 1;
        const bool ev = (p & 1) == 0;
        const int  ia = ev ? (j - 1) : j;
        const int  ib = ev ? j : (j + 1);
        const bool va = ia >= 0;
        const bool vb = ib <= 63;
        const int  c0 = h * 64;
        float acc = 0.f;
        for (int ci = c0; ci < c0 + 64; ++ci) {
            float4 w = *(const float4*)(Wc3 + (ci << 2));
            const float* xr = B + ci * 68;
            float xa = va ? xr[ia] : 0.f;
            float xb = vb ? xr[ib] : 0.f;
            float ca = ev ? w.x : w.y;
            float cb = ev ? w.z : w.w;
            acc += xa * ca + xb * cb;
        }
        part[t] = acc;
        __syncthreads();
        if (t < NF) {
            float v = bc3[0] + part[t] + part[t + 128];
            vseq[t] = v * v;
        }
    }
    __syncthreads();

    // ---------------- exponential decay recurrence: warp scan --------------------
    if (warp == 0) {
        const float d = s_decay;
        float4 u = *(const float4*)(vseq + lane * 4);
        float p0 = u.x;
        float p1 = fmaf(d, p0, u.y);
        float p2 = fmaf(d, p1, u.z);
        float p3 = fmaf(d, p2, u.w);
        const float d2 = d * d;
        const float d4 = d2 * d2;
        float V = p3;
        float m = d4;
#pragma unroll
        for (int off = 1; off < 32; off <<= 1) {
            float up = __shfl_up_sync(0xffffffffu, V, off);
            if (lane >= off) V = fmaf(m, up, V);
            m = m * m;
        }
        float C = __shfl_up_sync(0xffffffffu, V, 1);
        if (lane == 0) C = 0.f;
        float4 o;
        o.x = fmaf(C, d,      p0);
        o.y = fmaf(C, d2,     p1);
        o.z = fmaf(C, d2 * d, p2);
        o.w = fmaf(C, d4,     p3);
        *(float4*)(vseq + lane * 4) = o;
    }
    __syncthreads();
    // fused (value, slope) pairs; vd[127].y = 0 absorbs the i1 clamp
    if (t < NF) {
        float a = vseq[t];
        float b = (t < NF - 1) ? (vseq[t + 1] - a) : 0.f;
        vd[t] = make_float2(a, b);
    }
    __syncthreads();

    // ---------------- linear interp 128 -> 32768, multiply by noise --------------
    // pos(n) = (n+0.5)/256 - 0.5; per iter n += 1024 => pos += 4.0 exactly, so the
    // fractional weight is loop-invariant and i0 += 4. Only iter 0 can clamp low;
    // the high side never clamps (max pos = 127.498) and vd[127].y=0 covers i1.
    {
        const float4* np_ = (const float4*)(noise + (size_t)row * NS);
        float4*       op  = (float4*)(out + (size_t)row * NS);

        // iteration 0 (peeled, with low clamp)
        {
            float4 nz = np_[t];
            float4 r;
#pragma unroll
            for (int k = 0; k < 4; ++k) {
                float pos = fmaf((float)(4 * t + k), 0.00390625f, -0.498046875f);
                pos = fmaxf(pos, 0.f);
                int   i0 = (int)pos;
                float w  = pos - (float)i0;
                float2 s = vd[i0];
                ((float*)&r)[k] = fmaf(w, s.y, s.x) * ((const float*)&nz)[k];
            }
            op[t] = r;
        }

        // steady state: iterations 1..31
        int   i0v[4];
        float wv[4];
#pragma unroll
        for (int k = 0; k < 4; ++k) {
            float pos = fmaf((float)(4 * t + k + 1024), 0.00390625f, -0.498046875f);
            int   i = (int)pos;
            i0v[k] = i;
            wv[k]  = pos - (float)i;
        }
#pragma unroll 4
        for (int m = 1; m < 32; ++m) {
            float4 nz = np_[t + m * NT];
            float4 r;
#pragma unroll
            for (int k = 0; k < 4; ++k) {
                float2 s = vd[i0v[k]];
                ((float*)&r)[k] = fmaf(wv[k], s.y, s.x) * ((const float*)&nz)[k];
                i0v[k] += 4;
            }
            op[t + m * NT] = r;
        }
    }
}

extern "C" void kernel_launch(void* const* d_in, const int* in_sizes, int n_in,
                              void* d_out, int out_size)
{
    (void)in_sizes; (void)n_in; (void)out_size;
    const float* x    = (const float*)d_in[0];
    const float* noise= (const float*)d_in[1];
    const float* Wup  = (const float*)d_in[2];
    const float* bup  = (const float*)d_in[3];
    const float* Wd0  = (const float*)d_in[4];
    const float* bd0  = (const float*)d_in[5];
    const float* Wd1  = (const float*)d_in[6];
    const float* bd1  = (const float*)d_in[7];
    const float* Wd2  = (const float*)d_in[8];
    const float* bd2  = (const float*)d_in[9];
    const float* Wdo  = (const float*)d_in[10];
    const float* bdo  = (const float*)d_in[11];
    const float* Wc0  = (const float*)d_in[12];
    const float* bc0  = (const float*)d_in[13];
    const float* Wc1  = (const float*)d_in[14];
    const float* bc1  = (const float*)d_in[15];
    const float* Wc2  = (const float*)d_in[16];
    const float* bc2  = (const float*)d_in[17];
    const float* Wc3  = (const float*)d_in[18];
    const float* bc3  = (const float*)d_in[19];
    float* out = (float*)d_out;

    cudaFuncSetAttribute(npg_kernel, cudaFuncAttributeMaxDynamicSharedMemorySize, SMEM_BYTES);
    npg_kernel<<<BE, NT, SMEM_BYTES>>>(
        x, noise, Wup, bup, Wd0, bd0, Wd1, bd1, Wd2, bd2, Wdo, bdo,
        Wc0, bc0, Wc1, bc1, Wc2, bc2, Wc3, bc3, out);
}

// round 10
// speedup vs baseline: 1.0164x; 1.0164x over previous
#include <cuda_runtime.h>
#include <math.h>

#define DCH   128
#define BE    1024
#define NF    128
#define NS    32768
#define NT    256      // threads per CTA

// Dynamic smem (floats) — natural layouts (R4), strides 12/20/36/68
#define A_OFF    0
#define A_SIZE   (128*36)     // up-proj out (12/row), L2 out (36/row)
#define B_OFF    (A_OFF + A_SIZE)
#define B_SIZE   (128*68)     // L1 out (20/row), L3 out (68/row)
#define XF_OFF   (B_OFF + B_SIZE)
#define XFP_OFF  (XF_OFF + 128)
#define VS_OFF   (XFP_OFF + 256)
#define VD_OFF   (VS_OFF + 128)
#define PART_OFF (VD_OFF + 256)
#define SMEM_FLOATS (PART_OFF + 256)
#define SMEM_BYTES  (SMEM_FLOATS * 4)

typedef unsigned long long u64;

__device__ __forceinline__ float leaky(float v) { return v > 0.f ? v : 0.2f * v; }

__device__ __forceinline__ u64 pk(float a, float b) {
    u64 r; asm("mov.b64 %0, {%1,%2};" : "=l"(r) : "f"(a), "f"(b)); return r;
}
__device__ __forceinline__ void upk(u64 v, float& a, float& b) {
    asm("mov.b64 {%0,%1}, %2;" : "=f"(a), "=f"(b) : "l"(v));
}
__device__ __forceinline__ void f2fma(u64& d, u64 a, u64 b) {
    asm("fma.rn.f32x2 %0, %1, %2, %0;" : "+l"(d) : "l"(a), "l"(b));
}

// Transposed conv (k=4, s=2, p=1), JAX conv_transpose (no flip):
//   y[2j]   = sum_ci x[j-1]*w0 + x[j]*w2
//   y[2j+1] = sum_ci x[j]  *w1 + x[j+1]*w3
// acc2[j] += xp[j]*(w0,w1) + xp[j+1]*(w2,w3), xp[j]=(x[j-1],x[j]).
// x chunk loaded as ulonglong2: the aligned halves (x0,x1),(x2,x3) are FREE
// xp operands (register aliases); only (x1,x2) and (x3,next) need a pack MOV.
// Thread (co, h in {0,1}) computes output pairs j in [h*NJ, (h+1)*NJ).
template <int LIN, int SIN, int SOUT>
__device__ __forceinline__ void tconv(
    const float* __restrict__ W, const float* __restrict__ bias,
    const float* __restrict__ xin, float* __restrict__ yout,
    int co, int h)
{
    constexpr int NJ = LIN / 2;      // output pairs per thread
    constexpr int NC = NJ / 4;       // 16B x-chunks per ci
    const float bv = bias[co];
    u64 acc[NJ];
    {
        u64 bp = pk(bv, bv);
#pragma unroll
        for (int j = 0; j < NJ; ++j) acc[j] = bp;
    }
    const int j0f = h * NJ;          // first x element this thread touches

    for (int ci = 0; ci < DCH; ++ci) {
        ulonglong2 wq = *(const ulonglong2*)(W + ((ci * DCH + co) << 2)); // (w0,w1),(w2,w3)
        const float* xr = xin + ci * SIN + j0f;
        float prev = (h == 0) ? 0.f : xr[-1];
        float xend = (h == 1) ? 0.f : xr[NJ];
        const ulonglong2* xq = (const ulonglong2*)xr;
        ulonglong2 q = xq[0];
        float f1, f2, f3, fx;
        upk(q.x, fx, f1);            // fx = x0 (aliases)
        upk(q.y, f2, f3);
        u64 p0 = pk(prev, fx);
#pragma unroll
        for (int m = 0; m < NC; ++m) {
            ulonglong2 qn;
            float g0, g1, g2, g3;
            if (m + 1 < NC) qn = xq[m + 1];
            else { qn.x = pk(xend, 0.f); qn.y = 0ull; }
            upk(qn.x, g0, g1);
            upk(qn.y, g2, g3);
            u64 p2 = pk(f1, f2);
            u64 p4 = pk(f3, g0);
            f2fma(acc[4*m+0], p0,  wq.x); f2fma(acc[4*m+0], q.x, wq.y);
            f2fma(acc[4*m+1], q.x, wq.x); f2fma(acc[4*m+1], p2,  wq.y);
            f2fma(acc[4*m+2], p2,  wq.x); f2fma(acc[4*m+2], q.y, wq.y);
            f2fma(acc[4*m+3], q.y, wq.x); f2fma(acc[4*m+3], p4,  wq.y);
            p0 = p4;
            q = qn; f1 = g1; f2 = g2; f3 = g3;
        }
    }

    float* yr = yout + co * SOUT + 2 * j0f;
#pragma unroll
    for (int m = 0; m < NJ / 2; ++m) {
        float a0, a1, b0, b1;
        upk(acc[2*m],   a0, a1);
        upk(acc[2*m+1], b0, b1);
        float4 v;
        v.x = leaky(a0); v.y = leaky(a1);
        v.z = leaky(b0); v.w = leaky(b1);
        *(float4*)(yr + 4*m) = v;
    }
}

__global__ void __launch_bounds__(NT, 4) npg_kernel(
    const float* __restrict__ x,    const float* __restrict__ noise,
    const float* __restrict__ Wup,  const float* __restrict__ bup,
    const float* __restrict__ Wd0,  const float* __restrict__ bd0,
    const float* __restrict__ Wd1,  const float* __restrict__ bd1,
    const float* __restrict__ Wd2,  const float* __restrict__ bd2,
    const float* __restrict__ Wdo,  const float* __restrict__ bdo,
    const float* __restrict__ Wc0,  const float* __restrict__ bc0,
    const float* __restrict__ Wc1,  const float* __restrict__ bc1,
    const float* __restrict__ Wc2,  const float* __restrict__ bc2,
    const float* __restrict__ Wc3,  const float* __restrict__ bc3,
    float* __restrict__ out)
{
    extern __shared__ float smem[];
    float*  A    = smem + A_OFF;
    float*  B    = smem + B_OFF;
    float*  xf   = smem + XF_OFF;
    float*  xfp  = smem + XFP_OFF;   // (x, x) duplicated pairs for up-proj
    float*  vseq = smem + VS_OFF;
    float2* vd   = (float2*)(smem + VD_OFF);
    float*  part = smem + PART_OFF;
    __shared__ float s_decay;

    const int row  = blockIdx.x;
    const int t    = threadIdx.x;
    const int lane = t & 31;
    const int warp = t >> 5;
    const int co   = t & 127;
    const int h    = t >> 7;

    if (t < DCH) {
        float xv = x[row * DCH + t];
        xf[t] = xv;
        ((float2*)xfp)[t] = make_float2(xv, xv);
    }
    __syncthreads();

    // ---------------- decay head: 3x (D->D leaky) -> D->1 sigmoid ----------------
    {
        float* h0 = A;
        float* h1 = A + DCH;
        if (t < DCH) h0[t] = xf[t];
        __syncthreads();
        const float* Ws[3] = {Wd0, Wd1, Wd2};
        const float* bs[3] = {bd0, bd1, bd2};
        float* cur = h0;
        float* nxt = h1;
        for (int L = 0; L < 3; ++L) {
            const float* W = Ws[L];
            const int d0 = h * 64;
            float s0 = 0.f, s1 = 0.f, s2 = 0.f, s3 = 0.f;
            for (int dd = d0; dd < d0 + 64; dd += 4) {
                s0 += cur[dd+0] * W[(dd+0) * DCH + co];
                s1 += cur[dd+1] * W[(dd+1) * DCH + co];
                s2 += cur[dd+2] * W[(dd+2) * DCH + co];
                s3 += cur[dd+3] * W[(dd+3) * DCH + co];
            }
            part[t] = (s0 + s1) + (s2 + s3);
            __syncthreads();
            if (t < DCH) nxt[t] = leaky(bs[L][t] + part[t] + part[t + 128]);
            __syncthreads();
            float* tmp = cur; cur = nxt; nxt = tmp;
        }
        float p = (t < DCH) ? cur[t] * Wdo[t] : 0.f;
#pragma unroll
        for (int off = 16; off > 0; off >>= 1) p += __shfl_xor_sync(0xffffffffu, p, off);
        if (lane == 0) part[warp] = p;
        __syncthreads();
        if (t == 0) {
            float s = bdo[0];
            for (int wgi = 0; wgi < NT / 32; ++wgi) s += part[wgi];
            s_decay = 0.8f + 0.2f / (1.f + expf(-s));
        }
        __syncthreads();
    }

    // ------------- up projection: xf @ Wup -> natural [128][8] in A (stride 12) --
    // thread (co, h) computes output columns [4h, 4h+4)
    {
        float4 bvv = *(const float4*)(bup + co * 8 + 4 * h);
        u64 a01 = pk(bvv.x, bvv.y);
        u64 a23 = pk(bvv.z, bvv.w);
        const float* wr  = Wup + co * 8 + 4 * h;
        const u64*   xfq = (const u64*)xfp;
        for (int dd = 0; dd < DCH; ++dd) {
            ulonglong2 wq = *(const ulonglong2*)(wr + dd * (DCH * 8));
            u64 xx = xfq[dd];
            f2fma(a01, xx, wq.x);
            f2fma(a23, xx, wq.y);
        }
        __syncthreads();   // decay phase fully done with A
        float4 o;
        upk(a01, o.x, o.y);
        upk(a23, o.z, o.w);
        *(float4*)(A + co * 12 + 4 * h) = o;
        __syncthreads();
    }

    // ---------------- transposed conv stack: 8 -> 16 -> 32 -> 64 -----------------
    tconv<8,  12, 20>(Wc0, bc0, A, B, co, h);
    __syncthreads();
    tconv<16, 20, 36>(Wc1, bc1, B, A, co, h);
    __syncthreads();
    tconv<32, 36, 68>(Wc2, bc2, A, B, co, h);
    __syncthreads();

    // ---------------- final tconv to 1 channel (64 -> 128), square ---------------
    {
        const int  p  = co;
        const int  j  = p >> 1;
        const bool ev = (p & 1) == 0;
        const int  ia = ev ? (j - 1) : j;
        const int  ib = ev ? j : (j + 1);
        const bool va = ia >= 0;
        const bool vb = ib <= 63;
        const int  c0 = h * 64;
        float acc = 0.f;
        for (int ci = c0; ci < c0 + 64; ++ci) {
            float4 w = *(const float4*)(Wc3 + (ci << 2));
            const float* xr = B + ci * 68;
            float xa = va ? xr[ia] : 0.f;
            float xb = vb ? xr[ib] : 0.f;
            float ca = ev ? w.x : w.y;
            float cb = ev ? w.z : w.w;
            acc += xa * ca + xb * cb;
        }
        part[t] = acc;
        __syncthreads();
        if (t < NF) {
            float v = bc3[0] + part[t] + part[t + 128];
            vseq[t] = v * v;
        }
    }
    __syncthreads();

    // ---------------- exponential decay recurrence: warp scan --------------------
    if (warp == 0) {
        const float d = s_decay;
        float4 u = *(const float4*)(vseq + lane * 4);
        float p0 = u.x;
        float p1 = fmaf(d, p0, u.y);
        float p2 = fmaf(d, p1, u.z);
        float p3 = fmaf(d, p2, u.w);
        const float d2 = d * d;
        const float d4 = d2 * d2;
        float V = p3;
        float m = d4;
#pragma unroll
        for (int off = 1; off < 32; off <<= 1) {
            float up = __shfl_up_sync(0xffffffffu, V, off);
            if (lane >= off) V = fmaf(m, up, V);
            m = m * m;
        }
        float C = __shfl_up_sync(0xffffffffu, V, 1);
        if (lane == 0) C = 0.f;
        float4 o;
        o.x = fmaf(C, d,      p0);
        o.y = fmaf(C, d2,     p1);
        o.z = fmaf(C, d2 * d, p2);
        o.w = fmaf(C, d4,     p3);
        *(float4*)(vseq + lane * 4) = o;
    }
    __syncthreads();
    // fused (value, slope) pairs; vd[127].y = 0 absorbs the i1 clamp
    if (t < NF) {
        float a = vseq[t];
        float b = (t < NF - 1) ? (vseq[t + 1] - a) : 0.f;
        vd[t] = make_float2(a, b);
    }
    __syncthreads();

    // ---------------- linear interp 128 -> 32768, multiply by noise --------------
    // pos(n) = (n+0.5)/256 - 0.5; per iter n += 1024 => pos += 4.0 exactly:
    // fractional weight loop-invariant, i0 += 4. Only iter 0 can clamp low;
    // high side never clamps (max pos = 127.498) and vd[127].y=0 covers i1.
    {
        const float4* np_ = (const float4*)(noise + (size_t)row * NS);
        float4*       op  = (float4*)(out + (size_t)row * NS);

        // iteration 0 (peeled, with low clamp)
        {
            float4 nz = np_[t];
            float4 r;
#pragma unroll
            for (int k = 0; k < 4; ++k) {
                float pos = fmaf((float)(4 * t + k), 0.00390625f, -0.498046875f);
                pos = fmaxf(pos, 0.f);
                int   i0 = (int)pos;
                float w  = pos - (float)i0;
                float2 s = vd[i0];
                ((float*)&r)[k] = fmaf(w, s.y, s.x) * ((const float*)&nz)[k];
            }
            op[t] = r;
        }

        // steady state: iterations 1..31
        int   i0v[4];
        float wv[4];
#pragma unroll
        for (int k = 0; k < 4; ++k) {
            float pos = fmaf((float)(4 * t + k + 1024), 0.00390625f, -0.498046875f);
            int   i = (int)pos;
            i0v[k] = i;
            wv[k]  = pos - (float)i;
        }
#pragma unroll 4
        for (int m = 1; m < 32; ++m) {
            float4 nz = np_[t + m * NT];
            float4 r;
#pragma unroll
            for (int k = 0; k < 4; ++k) {
                float2 s = vd[i0v[k]];
                ((float*)&r)[k] = fmaf(wv[k], s.y, s.x) * ((const float*)&nz)[k];
                i0v[k] += 4;
            }
            op[t + m * NT] = r;
        }
    }
}

extern "C" void kernel_launch(void* const* d_in, const int* in_sizes, int n_in,
                              void* d_out, int out_size)
{
    (void)in_sizes; (void)n_in; (void)out_size;
    const float* x    = (const float*)d_in[0];
    const float* noise= (const float*)d_in[1];
    const float* Wup  = (const float*)d_in[2];
    const float* bup  = (const float*)d_in[3];
    const float* Wd0  = (const float*)d_in[4];
    const float* bd0  = (const float*)d_in[5];
    const float* Wd1  = (const float*)d_in[6];
    const float* bd1  = (const float*)d_in[7];
    const float* Wd2  = (const float*)d_in[8];
    const float* bd2  = (const float*)d_in[9];
    const float* Wdo  = (const float*)d_in[10];
    const float* bdo  = (const float*)d_in[11];
    const float* Wc0  = (const float*)d_in[12];
    const float* bc0  = (const float*)d_in[13];
    const float* Wc1  = (const float*)d_in[14];
    const float* bc1  = (const float*)d_in[15];
    const float* Wc2  = (const float*)d_in[16];
    const float* bc2  = (const float*)d_in[17];
    const float* Wc3  = (const float*)d_in[18];
    const float* bc3  = (const float*)d_in[19];
    float* out = (float*)d_out;

    cudaFuncSetAttribute(npg_kernel, cudaFuncAttributeMaxDynamicSharedMemorySize, SMEM_BYTES);
    npg_kernel<<<BE, NT, SMEM_BYTES>>>(
        x, noise, Wup, bup, Wd0, bd0, Wd1, bd1, Wd2, bd2, Wdo, bdo,
        Wc0, bc0, Wc1, bc1, Wc2, bc2, Wc3, bc3, out);
}